// round 9
// baseline (speedup 1.0000x reference)
#include <cuda_runtime.h>
#include <cstdint>

// Problem constants (fixed by the dataset)
#define BATCH 2
#define NPTS  16384
#define CH    64
#define SPTS  4096        // npoint
#define KNB   32          // nsample
#define R2    0.16f       // 0.4^2
#define OUTC  128

#define N_XYZ_OUT  (BATCH*SPTS*3)          // 24576
#define N_FEAT_OUT (BATCH*OUTC*SPTS)       // 1048576
#define OFF_FEAT   N_XYZ_OUT
#define OFF_SAMP   (N_XYZ_OUT + N_FEAT_OUT)

// Scratch (no allocation allowed -> device globals)
__device__ int g_idx[BATCH*SPTS*KNB];
__device__ __align__(16) float g_featT[(size_t)BATCH*NPTS*CH];
__device__ __align__(16) float4 g_xyzw[BATCH*NPTS];

// ---------------------------------------------------------------------------
// f32x2 packed-FMA helpers (sm_103a FFMA2)
// ---------------------------------------------------------------------------
__device__ __forceinline__ void ffma2(uint64_t& acc, uint64_t a, uint64_t b) {
    asm("fma.rn.f32x2 %0, %1, %2, %3;" : "=l"(acc) : "l"(a), "l"(b), "l"(acc));
}
__device__ __forceinline__ uint64_t pack2(float v) {
    uint64_t r;
    asm("mov.b64 %0, {%1, %1};" : "=l"(r) : "r"(__float_as_uint(v)));
    return r;
}
__device__ __forceinline__ uint64_t packab(float a, float b) {
    uint64_t r;
    asm("mov.b64 %0, {%1, %2};" : "=l"(r) : "r"(__float_as_uint(a)), "r"(__float_as_uint(b)));
    return r;
}
__device__ __forceinline__ void unpack2(uint64_t p, float& lo, float& hi) {
    unsigned a, b;
    asm("mov.b64 {%0, %1}, %2;" : "=r"(a), "=r"(b) : "l"(p));
    lo = __uint_as_float(a); hi = __uint_as_float(b);
}

// ---------------------------------------------------------------------------
// Kernel 0: pack xyz + precomputed squared norm into float4
// ---------------------------------------------------------------------------
__global__ void prep_kernel(const float* __restrict__ xyz) {
    int i = blockIdx.x * blockDim.x + threadIdx.x;
    if (i >= BATCH * NPTS) return;
    float px = xyz[i*3+0], py = xyz[i*3+1], pz = xyz[i*3+2];
    float pp = px*px + py*py + pz*pz;
    g_xyzw[i] = make_float4(px, py, pz, pp);
}

// ---------------------------------------------------------------------------
// Kernel 1: ball query. One warp per centroid, 64 candidates/iter,
// one-tile-ahead prefetch (4 LDG.128 in flight), early exit at 32 hits.
// ---------------------------------------------------------------------------
__device__ __forceinline__ void bq_step(float4 q, float4 p, int j, int lane,
                                        int* idx, int& cnt, bool& haveFirst, int& firstIdx) {
    float dot = q.x*p.x + q.y*p.y + q.z*p.z;
    float d2  = q.w + p.w - 2.0f*dot;       // same formula as reference
    bool hit = d2 < R2;
    unsigned mask = __ballot_sync(0xffffffffu, hit);
    if (mask && !haveFirst) {
        firstIdx = __shfl_sync(0xffffffffu, j, __ffs(mask) - 1);
        haveFirst = true;
    }
    int pos = cnt + __popc(mask & ((1u << lane) - 1u));
    if (hit && pos < KNB) idx[pos] = j;
    cnt += __popc(mask);
}

__global__ void bq_kernel() {
    int w    = (blockIdx.x * blockDim.x + threadIdx.x) >> 5;
    int lane = threadIdx.x & 31;
    if (w >= BATCH * SPTS) return;
    int b = w / SPTS, s = w % SPTS;
    const float4* xb4 = g_xyzw + (size_t)b * NPTS;
    float4 q = xb4[s];
    int* idx = g_idx + (size_t)w * KNB;
    int cnt = 0;
    int firstIdx = 0;
    bool haveFirst = false;

    // prime: current tile (64) + next tile (64)
    float4 c0 = xb4[lane],      c1 = xb4[32 + lane];
    float4 n0 = xb4[64 + lane], n1 = xb4[96 + lane];

    for (int j0 = 0; j0 < NPTS && cnt < KNB; j0 += 64) {
        float4 p0 = c0, p1 = c1;
        c0 = n0; c1 = n1;
        int i0 = j0 + 128 + lane;      if (i0 >= NPTS) i0 -= NPTS;   // wrap; unused tiles
        int i1 = j0 + 160 + lane;      if (i1 >= NPTS) i1 -= NPTS;
        n0 = xb4[i0]; n1 = xb4[i1];
        bq_step(q, p0, j0 + lane,      lane, idx, cnt, haveFirst, firstIdx);
        bq_step(q, p1, j0 + 32 + lane, lane, idx, cnt, haveFirst, firstIdx);
    }
    if (cnt < KNB && lane >= cnt) idx[lane] = firstIdx;
}

// ---------------------------------------------------------------------------
// Kernel 2: transpose features [B,C,N] -> [B,N,C]
// ---------------------------------------------------------------------------
__global__ void transpose_kernel(const float* __restrict__ f) {
    __shared__ float tile[32][33];
    int b  = blockIdx.z;
    int c0 = blockIdx.y * 32;
    int n0 = blockIdx.x * 32;
    int tx = threadIdx.x, ty = threadIdx.y;
    const float* src = f + ((size_t)b * CH) * NPTS;
    #pragma unroll
    for (int r = ty; r < 32; r += 8)
        tile[r][tx] = src[(size_t)(c0 + r) * NPTS + n0 + tx];
    __syncthreads();
    float* dst = g_featT + ((size_t)b * NPTS) * CH;
    #pragma unroll
    for (int r = ty; r < 32; r += 8)
        dst[(size_t)(n0 + r) * CH + c0 + tx] = tile[tx][r];
}

// ---------------------------------------------------------------------------
// Kernel 3: trivial outputs
// ---------------------------------------------------------------------------
__global__ void misc_kernel(const float* __restrict__ xyz, float* __restrict__ out) {
    int i = blockIdx.x * blockDim.x + threadIdx.x;
    if (i < N_XYZ_OUT) {
        int b = i / (SPTS * 3), r = i % (SPTS * 3);
        out[i] = xyz[(size_t)b * NPTS * 3 + r];
    }
    if (i < BATCH * SPTS) {
        out[OFF_SAMP + i] = (float)(i % SPTS);
    }
}

// ---------------------------------------------------------------------------
// Kernel 4: MLP + maxpool, WARP-PAIR per centroid.
// Each warp of the pair computes 32 of the 64 output channels per layer
// (acc = 16 u64), layer outputs exchanged via a small smem buffer.
// Inputs h stay register-resident (32 u64). W1/W2 + biases in smem
// (warp-uniform LDS.128 broadcasts); W3 via warp-uniform global loads.
// Registers ~150, 3 CTAs/SM (12 warps), all math FFMA2.
// ---------------------------------------------------------------------------
#define MLP_THREADS 128     // 4 warps = 2 centroids per CTA
#define XSTRIDE 66          // exchange row stride (floats): 2-way conflicts max

// smem layout (floats)
#define OFF_W1  0                        // 67*64 = 4288
#define OFF_W2  (OFF_W1 + 67*64)         // +4096 -> 8384
#define OFF_B1  (OFF_W2 + 64*64)         // 8384
#define OFF_B2  (OFF_B1 + 64)            // 8448
#define OFF_B3  (OFF_B2 + 64)            // 8512
#define OFF_X   (OFF_B3 + 128)           // 8640 : 2 pairs * 32 lanes * 66
#define SMEM_FLOATS (OFF_X + 2*32*XSTRIDE)   // 8640 + 4224 = 12864
#define SMEM_BYTES  (SMEM_FLOATS * 4)        // 51456 B -> 3 CTAs/SM

__global__ void __launch_bounds__(MLP_THREADS, 3)
mlp_kernel(const float* __restrict__ W1, const float* __restrict__ b1,
           const float* __restrict__ W2, const float* __restrict__ b2,
           const float* __restrict__ W3, const float* __restrict__ b3,
           float* __restrict__ out) {
    extern __shared__ float sm[];
    int t = threadIdx.x;
    for (int i = t; i < 67*64; i += MLP_THREADS) sm[OFF_W1 + i] = W1[i];
    for (int i = t; i < 64*64; i += MLP_THREADS) sm[OFF_W2 + i] = W2[i];
    if (t < 64)  sm[OFF_B1 + t] = b1[t];
    if (t < 64)  sm[OFF_B2 + t] = b2[t];
    if (t < 128) sm[OFF_B3 + t] = b3[t];
    __syncthreads();

    int lane = t & 31;
    int wrp  = t >> 5;        // 0..3
    int pair = wrp >> 1;      // centroid slot in CTA
    int half = wrp & 1;       // which 32 output channels this warp owns
    int cid  = blockIdx.x * 2 + pair;
    int b = cid / SPTS, s = cid % SPTS;

    // ---- gather this lane's neighbor (both warps of the pair gather) ----
    int n = g_idx[(size_t)cid * KNB + lane];
    uint64_t h[32];
    {
        const ulonglong2* fr = (const ulonglong2*)(g_featT + ((size_t)b * NPTS + n) * CH);
        #pragma unroll
        for (int i = 0; i < 16; i++) { ulonglong2 v = fr[i]; h[2*i] = v.x; h[2*i+1] = v.y; }
    }
    float4 pc = g_xyzw[(size_t)b * NPTS + s];
    float4 pn = g_xyzw[(size_t)b * NPTS + n];
    float gxyz[3] = {pn.x - pc.x, pn.y - pc.y, pn.z - pc.z};

    float* xrow = sm + OFF_X + pair * (32 * XSTRIDE) + lane * XSTRIDE;

    uint64_t acc[16];

    // ================= layer 1: 67 -> 64 (this warp: 32 outputs) =================
    {
        const ulonglong2* bb = (const ulonglong2*)(sm + OFF_B1 + half*32);
        #pragma unroll
        for (int i = 0; i < 8; i++) { ulonglong2 v = bb[i]; acc[2*i] = v.x; acc[2*i+1] = v.y; }
        #pragma unroll
        for (int c = 0; c < 3; c++) {
            uint64_t g2 = pack2(gxyz[c]);
            const ulonglong2* w = (const ulonglong2*)(sm + OFF_W1 + c*64 + half*32);
            #pragma unroll
            for (int i = 0; i < 8; i++) {
                ulonglong2 x = w[i];
                ffma2(acc[2*i],   g2, x.x);
                ffma2(acc[2*i+1], g2, x.y);
            }
        }
        #pragma unroll 4
        for (int cp = 0; cp < 32; cp++) {
            float lo, hi; unpack2(h[cp], lo, hi);
            uint64_t glo = pack2(lo), ghi = pack2(hi);
            const ulonglong2* w0 = (const ulonglong2*)(sm + OFF_W1 + (3 + 2*cp)*64 + half*32);
            const ulonglong2* w1 = (const ulonglong2*)(sm + OFF_W1 + (4 + 2*cp)*64 + half*32);
            #pragma unroll
            for (int i = 0; i < 8; i++) {
                ulonglong2 x = w0[i];
                ffma2(acc[2*i],   glo, x.x);
                ffma2(acc[2*i+1], glo, x.y);
            }
            #pragma unroll
            for (int i = 0; i < 8; i++) {
                ulonglong2 x = w1[i];
                ffma2(acc[2*i],   ghi, x.x);
                ffma2(acc[2*i+1], ghi, x.y);
            }
        }
        #pragma unroll
        for (int i = 0; i < 16; i++) {
            float lo, hi; unpack2(acc[i], lo, hi);
            *(uint64_t*)(xrow + half*32 + 2*i) = packab(fmaxf(lo, 0.0f), fmaxf(hi, 0.0f));
        }
    }
    __syncthreads();
    #pragma unroll
    for (int i = 0; i < 32; i++) h[i] = *(const uint64_t*)(xrow + 2*i);
    __syncthreads();

    // ================= layer 2: 64 -> 64 (this warp: 32 outputs) =================
    {
        const ulonglong2* bb = (const ulonglong2*)(sm + OFF_B2 + half*32);
        #pragma unroll
        for (int i = 0; i < 8; i++) { ulonglong2 v = bb[i]; acc[2*i] = v.x; acc[2*i+1] = v.y; }
        #pragma unroll 4
        for (int cp = 0; cp < 32; cp++) {
            float lo, hi; unpack2(h[cp], lo, hi);
            uint64_t glo = pack2(lo), ghi = pack2(hi);
            const ulonglong2* w0 = (const ulonglong2*)(sm + OFF_W2 + (2*cp    )*64 + half*32);
            const ulonglong2* w1 = (const ulonglong2*)(sm + OFF_W2 + (2*cp + 1)*64 + half*32);
            #pragma unroll
            for (int i = 0; i < 8; i++) {
                ulonglong2 x = w0[i];
                ffma2(acc[2*i],   glo, x.x);
                ffma2(acc[2*i+1], glo, x.y);
            }
            #pragma unroll
            for (int i = 0; i < 8; i++) {
                ulonglong2 x = w1[i];
                ffma2(acc[2*i],   ghi, x.x);
                ffma2(acc[2*i+1], ghi, x.y);
            }
        }
        #pragma unroll
        for (int i = 0; i < 16; i++) {
            float lo, hi; unpack2(acc[i], lo, hi);
            *(uint64_t*)(xrow + half*32 + 2*i) = packab(fmaxf(lo, 0.0f), fmaxf(hi, 0.0f));
        }
    }
    __syncthreads();
    #pragma unroll
    for (int i = 0; i < 32; i++) h[i] = *(const uint64_t*)(xrow + 2*i);

    // ================= layer 3: 64 -> 128 (this warp: 64 outputs in 2 passes) ====
    // W3 via warp-uniform global loads (L1-resident, smem freed for occupancy).
    #pragma unroll 1
    for (int pass = 0; pass < 2; pass++) {
        int d0 = half*64 + pass*32;
        {
            const ulonglong2* bb = (const ulonglong2*)(sm + OFF_B3 + d0);
            #pragma unroll
            for (int i = 0; i < 8; i++) { ulonglong2 v = bb[i]; acc[2*i] = v.x; acc[2*i+1] = v.y; }
        }
        #pragma unroll 4
        for (int cp = 0; cp < 32; cp++) {
            float lo, hi; unpack2(h[cp], lo, hi);
            uint64_t glo = pack2(lo), ghi = pack2(hi);
            const ulonglong2* w0 = (const ulonglong2*)(W3 + (2*cp    )*128 + d0);
            const ulonglong2* w1 = (const ulonglong2*)(W3 + (2*cp + 1)*128 + d0);
            #pragma unroll
            for (int i = 0; i < 8; i++) {
                ulonglong2 x = w0[i];
                ffma2(acc[2*i],   glo, x.x);
                ffma2(acc[2*i+1], glo, x.y);
            }
            #pragma unroll
            for (int i = 0; i < 8; i++) {
                ulonglong2 x = w1[i];
                ffma2(acc[2*i],   ghi, x.x);
                ffma2(acc[2*i+1], ghi, x.y);
            }
        }
        // relu + warp maxpool over neighbors + store
        #pragma unroll
        for (int i = 0; i < 16; i++) {
            float lo, hi; unpack2(acc[i], lo, hi);
            lo = fmaxf(lo, 0.0f);
            hi = fmaxf(hi, 0.0f);
            #pragma unroll
            for (int sh = 16; sh >= 1; sh >>= 1) {
                lo = fmaxf(lo, __shfl_xor_sync(0xffffffffu, lo, sh));
                hi = fmaxf(hi, __shfl_xor_sync(0xffffffffu, hi, sh));
            }
            if (lane == 0) {
                int d = d0 + 2*i;
                out[OFF_FEAT + ((size_t)b * OUTC + d    ) * SPTS + s] = lo;
                out[OFF_FEAT + ((size_t)b * OUTC + d + 1) * SPTS + s] = hi;
            }
        }
    }
}

// ---------------------------------------------------------------------------
extern "C" void kernel_launch(void* const* d_in, const int* in_sizes, int n_in,
                              void* d_out, int out_size) {
    const float* xyz      = (const float*)d_in[0];
    const float* features = (const float*)d_in[1];
    const float* W1 = (const float*)d_in[2];
    const float* b1 = (const float*)d_in[3];
    const float* W2 = (const float*)d_in[4];
    const float* b2 = (const float*)d_in[5];
    const float* W3 = (const float*)d_in[6];
    const float* b3 = (const float*)d_in[7];
    float* out = (float*)d_out;

    // pack xyz + |p|^2
    prep_kernel<<<(BATCH*NPTS + 255)/256, 256>>>(xyz);

    // ball query
    bq_kernel<<<(BATCH*SPTS*32)/256, 256>>>();

    // feature transpose [B,C,N] -> [B,N,C]
    {
        dim3 g(NPTS/32, CH/32, BATCH);
        dim3 blk(32, 8);
        transpose_kernel<<<g, blk>>>(features);
    }

    // trivial outputs
    misc_kernel<<<(N_XYZ_OUT + 255)/256, 256>>>(xyz, out);

    // MLP + maxpool: warp-pair per centroid, 2 centroids per 128-thread CTA
    static bool attr_done = false;
    if (!attr_done) {
        cudaFuncSetAttribute(mlp_kernel, cudaFuncAttributeMaxDynamicSharedMemorySize, SMEM_BYTES);
        attr_done = true;
    }
    mlp_kernel<<<(BATCH*SPTS)/2, MLP_THREADS, SMEM_BYTES>>>(W1, b1, W2, b2, W3, b3, out);
}

// round 11
// speedup vs baseline: 1.3131x; 1.3131x over previous
#include <cuda_runtime.h>
#include <cstdint>

// Problem constants (fixed by the dataset)
#define BATCH 2
#define NPTS  16384
#define CH    64
#define SPTS  4096        // npoint
#define KNB   32          // nsample
#define R2    0.16f       // 0.4^2
#define OUTC  128

#define N_XYZ_OUT  (BATCH*SPTS*3)          // 24576
#define N_FEAT_OUT (BATCH*OUTC*SPTS)       // 1048576
#define OFF_FEAT   N_XYZ_OUT
#define OFF_SAMP   (N_XYZ_OUT + N_FEAT_OUT)

// Scratch (no allocation allowed -> device globals)
__device__ int g_idx[BATCH*SPTS*KNB];
__device__ __align__(16) float g_featT[(size_t)BATCH*NPTS*CH];
__device__ __align__(16) float4 g_xyzw[BATCH*NPTS];

// ---------------------------------------------------------------------------
// f32x2 packed-FMA helpers (sm_103a FFMA2)
// ---------------------------------------------------------------------------
__device__ __forceinline__ void ffma2(uint64_t& acc, uint64_t a, uint64_t b) {
    asm("fma.rn.f32x2 %0, %1, %2, %3;" : "=l"(acc) : "l"(a), "l"(b), "l"(acc));
}
__device__ __forceinline__ uint64_t pack2(float v) {
    uint64_t r;
    asm("mov.b64 %0, {%1, %1};" : "=l"(r) : "r"(__float_as_uint(v)));
    return r;
}
__device__ __forceinline__ uint64_t packab(float a, float b) {
    uint64_t r;
    asm("mov.b64 %0, {%1, %2};" : "=l"(r) : "r"(__float_as_uint(a)), "r"(__float_as_uint(b)));
    return r;
}
__device__ __forceinline__ void unpack2(uint64_t p, float& lo, float& hi) {
    unsigned a, b;
    asm("mov.b64 {%0, %1}, %2;" : "=r"(a), "=r"(b) : "l"(p));
    lo = __uint_as_float(a); hi = __uint_as_float(b);
}

// ---------------------------------------------------------------------------
// Kernel 0: pack xyz + precomputed squared norm into float4
// ---------------------------------------------------------------------------
__global__ void prep_kernel(const float* __restrict__ xyz) {
    int i = blockIdx.x * blockDim.x + threadIdx.x;
    if (i >= BATCH * NPTS) return;
    float px = xyz[i*3+0], py = xyz[i*3+1], pz = xyz[i*3+2];
    float pp = px*px + py*py + pz*pz;
    g_xyzw[i] = make_float4(px, py, pz, pp);
}

// ---------------------------------------------------------------------------
// Kernel 1: ball query. One warp per centroid, 128 candidates per iteration.
// The 4 distance/ballot computations are independent (overlap in flight);
// only the cheap popc/insert chain is sequential. firstIdx derived from
// __ffs (no SHFL). Early exit checked every 128 candidates.
// ---------------------------------------------------------------------------
__global__ void bq_kernel() {
    int w    = (blockIdx.x * blockDim.x + threadIdx.x) >> 5;
    int lane = threadIdx.x & 31;
    if (w >= BATCH * SPTS) return;
    int b = w / SPTS, s = w % SPTS;
    const float4* xb4 = g_xyzw + (size_t)b * NPTS;
    float4 q = xb4[s];
    int* idx = g_idx + (size_t)w * KNB;
    int cnt = 0;
    int firstIdx = 0;
    bool haveFirst = false;
    unsigned lmask = (1u << lane) - 1u;

    float4 cur[4], nxt[4];
    #pragma unroll
    for (int t = 0; t < 4; t++) cur[t] = xb4[32*t + lane];
    #pragma unroll
    for (int t = 0; t < 4; t++) nxt[t] = xb4[128 + 32*t + lane];

    for (int j0 = 0; j0 < NPTS && cnt < KNB; j0 += 128) {
        // 4 independent distance tests + ballots
        unsigned m[4];
        bool hit[4];
        #pragma unroll
        for (int t = 0; t < 4; t++) {
            float4 p = cur[t];
            float dot = q.x*p.x + q.y*p.y + q.z*p.z;
            float d2  = q.w + p.w - 2.0f*dot;   // same formula as reference
            hit[t] = d2 < R2;
            m[t] = __ballot_sync(0xffffffffu, hit[t]);
        }
        // rotate + prefetch next 128 (wrapped indices harmless)
        #pragma unroll
        for (int t = 0; t < 4; t++) {
            cur[t] = nxt[t];
            int i = j0 + 256 + 32*t + lane;
            if (i >= NPTS) i -= NPTS;
            nxt[t] = xb4[i];
        }
        // sequential insertion (cheap ALU chain)
        #pragma unroll
        for (int t = 0; t < 4; t++) {
            if (m[t] && !haveFirst) {
                firstIdx = j0 + 32*t + (__ffs(m[t]) - 1);
                haveFirst = true;
            }
            int pos = cnt + __popc(m[t] & lmask);
            if (hit[t] && pos < KNB) idx[pos] = j0 + 32*t + lane;
            cnt += __popc(m[t]);
        }
    }
    if (cnt < KNB && lane >= cnt) idx[lane] = firstIdx;
}

// ---------------------------------------------------------------------------
// Kernel 2: transpose features [B,C,N] -> [B,N,C]
// ---------------------------------------------------------------------------
__global__ void transpose_kernel(const float* __restrict__ f) {
    __shared__ float tile[32][33];
    int b  = blockIdx.z;
    int c0 = blockIdx.y * 32;
    int n0 = blockIdx.x * 32;
    int tx = threadIdx.x, ty = threadIdx.y;
    const float* src = f + ((size_t)b * CH) * NPTS;
    #pragma unroll
    for (int r = ty; r < 32; r += 8)
        tile[r][tx] = src[(size_t)(c0 + r) * NPTS + n0 + tx];
    __syncthreads();
    float* dst = g_featT + ((size_t)b * NPTS) * CH;
    #pragma unroll
    for (int r = ty; r < 32; r += 8)
        dst[(size_t)(n0 + r) * CH + c0 + tx] = tile[tx][r];
}

// ---------------------------------------------------------------------------
// Kernel 3: trivial outputs
// ---------------------------------------------------------------------------
__global__ void misc_kernel(const float* __restrict__ xyz, float* __restrict__ out) {
    int i = blockIdx.x * blockDim.x + threadIdx.x;
    if (i < N_XYZ_OUT) {
        int b = i / (SPTS * 3), r = i % (SPTS * 3);
        out[i] = xyz[(size_t)b * NPTS * 3 + r];
    }
    if (i < BATCH * SPTS) {
        out[OFF_SAMP + i] = (float)(i % SPTS);
    }
}

// ---------------------------------------------------------------------------
// Kernel 4: gather + 3-layer MLP + maxpool, warp-per-centroid.
// Lane = neighbor k. Activations ping-pong in registers (packed f32x2);
// no smem activations, no barriers in the mainloop. All weights + biases
// in smem, accessed as warp-uniform LDS.128 broadcasts. All math FFMA2.
// L1/L2 single-pass (acc[32]); L3 in 4 passes of 32 outputs (acc[16],
// reduced + stored per pass) to cap peak registers. 128-thread CTAs,
// __launch_bounds__(128,3) -> 170 regs, 3 CTAs/SM = 12 warps/SM.
// ---------------------------------------------------------------------------
#define MLP_THREADS 128   // 4 warps -> 4 centroids per block

// smem layout (floats)
#define OFF_W1  0                        // 67*64 = 4288
#define OFF_W2  (OFF_W1 + 67*64)         // +4096
#define OFF_W3  (OFF_W2 + 64*64)         // +8192
#define OFF_B1  (OFF_W3 + 64*128)        // 16576
#define OFF_B2  (OFF_B1 + 64)
#define OFF_B3  (OFF_B2 + 64)
#define SMEM_FLOATS (OFF_B3 + 128)       // 16832
#define SMEM_BYTES  (SMEM_FLOATS * 4)    // 67328 B -> 3 CTAs/SM (202 KB)

__global__ void __launch_bounds__(MLP_THREADS, 3)
mlp_kernel(const float* __restrict__ W1, const float* __restrict__ b1,
           const float* __restrict__ W2, const float* __restrict__ b2,
           const float* __restrict__ W3, const float* __restrict__ b3,
           float* __restrict__ out) {
    extern __shared__ float sm[];
    int t = threadIdx.x;
    // stage all weights + biases once
    for (int i = t; i < 67*64;  i += MLP_THREADS) sm[OFF_W1 + i] = W1[i];
    for (int i = t; i < 64*64;  i += MLP_THREADS) sm[OFF_W2 + i] = W2[i];
    for (int i = t; i < 64*128; i += MLP_THREADS) sm[OFF_W3 + i] = W3[i];
    if (t < 64)  sm[OFF_B1 + t] = b1[t];
    if (t < 64)  sm[OFF_B2 + t] = b2[t];
    if (t < 128) sm[OFF_B3 + t] = b3[t];
    __syncthreads();

    int warp = blockIdx.x * (MLP_THREADS/32) + (t >> 5);   // centroid id
    int lane = t & 31;                                     // neighbor k
    int b = warp / SPTS, s = warp % SPTS;

    // ---- gather: this lane's neighbor point ----
    int n = g_idx[(size_t)warp * KNB + lane];
    uint64_t h[32];   // 64 packed activation channels
    {
        const ulonglong2* fr = (const ulonglong2*)(g_featT + ((size_t)b * NPTS + n) * CH);
        #pragma unroll
        for (int i = 0; i < 16; i++) { ulonglong2 v = fr[i]; h[2*i] = v.x; h[2*i+1] = v.y; }
    }
    float4 pc = g_xyzw[(size_t)b * NPTS + s];
    float4 pn = g_xyzw[(size_t)b * NPTS + n];
    float gxyz[3] = {pn.x - pc.x, pn.y - pc.y, pn.z - pc.z};

    {
        uint64_t acc[32];  // 64 packed outputs (L1/L2 only)

        // ================= layer 1: 67 -> 64 =================
        {
            const ulonglong2* bb = (const ulonglong2*)(sm + OFF_B1);
            #pragma unroll
            for (int i = 0; i < 16; i++) { ulonglong2 v = bb[i]; acc[2*i] = v.x; acc[2*i+1] = v.y; }
        }
        #pragma unroll
        for (int c = 0; c < 3; c++) {
            uint64_t g2 = pack2(gxyz[c]);
            const ulonglong2* w = (const ulonglong2*)(sm + OFF_W1 + c*64);
            #pragma unroll
            for (int i = 0; i < 16; i++) {
                ulonglong2 x = w[i];
                ffma2(acc[2*i],   g2, x.x);
                ffma2(acc[2*i+1], g2, x.y);
            }
        }
        #pragma unroll 2
        for (int cp = 0; cp < 32; cp++) {
            float lo, hi; unpack2(h[cp], lo, hi);
            uint64_t glo = pack2(lo), ghi = pack2(hi);
            const ulonglong2* w0 = (const ulonglong2*)(sm + OFF_W1 + (3 + 2*cp)*64);
            const ulonglong2* w1 = (const ulonglong2*)(sm + OFF_W1 + (4 + 2*cp)*64);
            #pragma unroll
            for (int i = 0; i < 16; i++) {
                ulonglong2 x = w0[i];
                ffma2(acc[2*i],   glo, x.x);
                ffma2(acc[2*i+1], glo, x.y);
            }
            #pragma unroll
            for (int i = 0; i < 16; i++) {
                ulonglong2 x = w1[i];
                ffma2(acc[2*i],   ghi, x.x);
                ffma2(acc[2*i+1], ghi, x.y);
            }
        }
        #pragma unroll
        for (int i = 0; i < 32; i++) {
            float lo, hi; unpack2(acc[i], lo, hi);
            h[i] = packab(fmaxf(lo, 0.0f), fmaxf(hi, 0.0f));
        }

        // ================= layer 2: 64 -> 64 =================
        {
            const ulonglong2* bb = (const ulonglong2*)(sm + OFF_B2);
            #pragma unroll
            for (int i = 0; i < 16; i++) { ulonglong2 v = bb[i]; acc[2*i] = v.x; acc[2*i+1] = v.y; }
        }
        #pragma unroll 2
        for (int cp = 0; cp < 32; cp++) {
            float lo, hi; unpack2(h[cp], lo, hi);
            uint64_t glo = pack2(lo), ghi = pack2(hi);
            const ulonglong2* w0 = (const ulonglong2*)(sm + OFF_W2 + (2*cp    )*64);
            const ulonglong2* w1 = (const ulonglong2*)(sm + OFF_W2 + (2*cp + 1)*64);
            #pragma unroll
            for (int i = 0; i < 16; i++) {
                ulonglong2 x = w0[i];
                ffma2(acc[2*i],   glo, x.x);
                ffma2(acc[2*i+1], glo, x.y);
            }
            #pragma unroll
            for (int i = 0; i < 16; i++) {
                ulonglong2 x = w1[i];
                ffma2(acc[2*i],   ghi, x.x);
                ffma2(acc[2*i+1], ghi, x.y);
            }
        }
        #pragma unroll
        for (int i = 0; i < 32; i++) {
            float lo, hi; unpack2(acc[i], lo, hi);
            h[i] = packab(fmaxf(lo, 0.0f), fmaxf(hi, 0.0f));
        }
    }

    // ===== layer 3: 64 -> 128, 4 passes of 32 outputs, fused relu+maxpool ====
    #pragma unroll 1
    for (int pass = 0; pass < 4; pass++) {
        int d0 = pass * 32;
        uint64_t acc[16];
        {
            const ulonglong2* bb = (const ulonglong2*)(sm + OFF_B3 + d0);
            #pragma unroll
            for (int i = 0; i < 8; i++) { ulonglong2 v = bb[i]; acc[2*i] = v.x; acc[2*i+1] = v.y; }
        }
        #pragma unroll 4
        for (int cp = 0; cp < 32; cp++) {
            float lo, hi; unpack2(h[cp], lo, hi);
            uint64_t glo = pack2(lo), ghi = pack2(hi);
            const ulonglong2* w0 = (const ulonglong2*)(sm + OFF_W3 + (2*cp    )*128 + d0);
            const ulonglong2* w1 = (const ulonglong2*)(sm + OFF_W3 + (2*cp + 1)*128 + d0);
            #pragma unroll
            for (int i = 0; i < 8; i++) {
                ulonglong2 x = w0[i];
                ffma2(acc[2*i],   glo, x.x);
                ffma2(acc[2*i+1], glo, x.y);
            }
            #pragma unroll
            for (int i = 0; i < 8; i++) {
                ulonglong2 x = w1[i];
                ffma2(acc[2*i],   ghi, x.x);
                ffma2(acc[2*i+1], ghi, x.y);
            }
        }
        // relu + warp maxpool over neighbors + store
        #pragma unroll
        for (int i = 0; i < 16; i++) {
            float lo, hi; unpack2(acc[i], lo, hi);
            lo = fmaxf(lo, 0.0f);
            hi = fmaxf(hi, 0.0f);
            #pragma unroll
            for (int sh = 16; sh >= 1; sh >>= 1) {
                lo = fmaxf(lo, __shfl_xor_sync(0xffffffffu, lo, sh));
                hi = fmaxf(hi, __shfl_xor_sync(0xffffffffu, hi, sh));
            }
            if (lane == 0) {
                int d = d0 + 2*i;
                out[OFF_FEAT + ((size_t)b * OUTC + d    ) * SPTS + s] = lo;
                out[OFF_FEAT + ((size_t)b * OUTC + d + 1) * SPTS + s] = hi;
            }
        }
    }
}

// ---------------------------------------------------------------------------
extern "C" void kernel_launch(void* const* d_in, const int* in_sizes, int n_in,
                              void* d_out, int out_size) {
    const float* xyz      = (const float*)d_in[0];
    const float* features = (const float*)d_in[1];
    const float* W1 = (const float*)d_in[2];
    const float* b1 = (const float*)d_in[3];
    const float* W2 = (const float*)d_in[4];
    const float* b2 = (const float*)d_in[5];
    const float* W3 = (const float*)d_in[6];
    const float* b3 = (const float*)d_in[7];
    float* out = (float*)d_out;

    // pack xyz + |p|^2
    prep_kernel<<<(BATCH*NPTS + 255)/256, 256>>>(xyz);

    // ball query: one warp per centroid, 128-wide chunks
    bq_kernel<<<(BATCH*SPTS*32)/256, 256>>>();

    // feature transpose [B,C,N] -> [B,N,C]
    {
        dim3 g(NPTS/32, CH/32, BATCH);
        dim3 blk(32, 8);
        transpose_kernel<<<g, blk>>>(features);
    }

    // trivial outputs
    misc_kernel<<<(N_XYZ_OUT + 255)/256, 256>>>(xyz, out);

    // MLP + maxpool: warp-per-centroid, 4 centroids per 128-thread CTA
    static bool attr_done = false;
    if (!attr_done) {
        cudaFuncSetAttribute(mlp_kernel, cudaFuncAttributeMaxDynamicSharedMemorySize, SMEM_BYTES);
        attr_done = true;
    }
    mlp_kernel<<<(BATCH*SPTS)/(MLP_THREADS/32), MLP_THREADS, SMEM_BYTES>>>(W1, b1, W2, b2, W3, b3, out);
}

// round 17
// speedup vs baseline: 2.1783x; 1.6589x over previous
#include <cuda_runtime.h>
#include <cuda_bf16.h>
#include <cstdint>

// Problem constants (fixed by the dataset)
#define BATCH 2
#define NPTS  16384
#define CH    64
#define SPTS  4096        // npoint
#define KNB   32          // nsample
#define R2    0.16f       // 0.4^2
#define OUTC  128

#define N_XYZ_OUT  (BATCH*SPTS*3)          // 24576
#define N_FEAT_OUT (BATCH*OUTC*SPTS)       // 1048576
#define OFF_FEAT   N_XYZ_OUT
#define OFF_SAMP   (N_XYZ_OUT + N_FEAT_OUT)

// Scratch (no allocation allowed -> device globals)
__device__ int g_idx[BATCH*SPTS*KNB];
__device__ __align__(16) float g_featT[(size_t)BATCH*NPTS*CH];
__device__ __align__(16) float4 g_xyzw[BATCH*NPTS];
// weights transposed to [N,K], split into bf16 hi/lo
__device__ __align__(16) __nv_bfloat16 g_w1h[64*128], g_w1l[64*128];
__device__ __align__(16) __nv_bfloat16 g_w2h[64*64],  g_w2l[64*64];
__device__ __align__(16) __nv_bfloat16 g_w3h[128*64], g_w3l[128*64];

// ===========================================================================
// mma.sync / ldmatrix helpers (baseline PTX, sm_80+; no 'a' features)
// ===========================================================================
__device__ __forceinline__ uint32_t smem_to_u32(const void* smem_ptr) {
    uint32_t addr;
    asm("{ .reg .u64 tmp; cvta.to.shared.u64 tmp, %1; cvt.u32.u64 %0, tmp; }"
        : "=r"(addr) : "l"(smem_ptr));
    return addr;
}
__device__ __forceinline__ void ldm_x4(uint32_t& r0, uint32_t& r1, uint32_t& r2,
                                       uint32_t& r3, uint32_t addr) {
    asm volatile("ldmatrix.sync.aligned.m8n8.x4.shared.b16 {%0,%1,%2,%3}, [%4];"
                 : "=r"(r0), "=r"(r1), "=r"(r2), "=r"(r3) : "r"(addr));
}
__device__ __forceinline__ void ldm_x2(uint32_t& r0, uint32_t& r1, uint32_t addr) {
    asm volatile("ldmatrix.sync.aligned.m8n8.x2.shared.b16 {%0,%1}, [%2];"
                 : "=r"(r0), "=r"(r1) : "r"(addr));
}
__device__ __forceinline__ void mma_bf16(float* d, uint32_t a0, uint32_t a1,
                                         uint32_t a2, uint32_t a3,
                                         uint32_t b0, uint32_t b1) {
    asm volatile("mma.sync.aligned.m16n8k16.row.col.f32.bf16.bf16.f32 "
                 "{%0,%1,%2,%3}, {%4,%5,%6,%7}, {%8,%9}, {%0,%1,%2,%3};"
                 : "+f"(d[0]), "+f"(d[1]), "+f"(d[2]), "+f"(d[3])
                 : "r"(a0), "r"(a1), "r"(a2), "r"(a3), "r"(b0), "r"(b1));
}
__device__ __forceinline__ uint32_t pack_bf2(float a, float b) {
    __nv_bfloat162 p;
    p.x = __float2bfloat16(a);
    p.y = __float2bfloat16(b);
    return *(uint32_t*)&p;
}

// ---------------------------------------------------------------------------
// Kernel 0: pack xyz + precomputed squared norm into float4
// ---------------------------------------------------------------------------
__global__ void prep_kernel(const float* __restrict__ xyz) {
    int i = blockIdx.x * blockDim.x + threadIdx.x;
    if (i >= BATCH * NPTS) return;
    float px = xyz[i*3+0], py = xyz[i*3+1], pz = xyz[i*3+2];
    float pp = px*px + py*py + pz*pz;
    g_xyzw[i] = make_float4(px, py, pz, pp);
}

// ---------------------------------------------------------------------------
// Kernel 0b: transpose + hi/lo bf16 split of weights into [N,K] layout
// ---------------------------------------------------------------------------
__global__ void wprep_kernel(const float* __restrict__ W1, const float* __restrict__ W2,
                             const float* __restrict__ W3) {
    int i = blockIdx.x * blockDim.x + threadIdx.x;
    if (i < 64*128) {               // W1T: [n=64][k=128], k<67 valid, rest zero
        int n = i >> 7, k = i & 127;
        float v = (k < 67) ? W1[k*64 + n] : 0.0f;
        __nv_bfloat16 h = __float2bfloat16(v);
        g_w1h[i] = h;
        g_w1l[i] = __float2bfloat16(v - __bfloat162float(h));
    }
    if (i < 64*64) {                // W2T: [n=64][k=64]
        int n = i >> 6, k = i & 63;
        float v = W2[k*64 + n];
        __nv_bfloat16 h = __float2bfloat16(v);
        g_w2h[i] = h;
        g_w2l[i] = __float2bfloat16(v - __bfloat162float(h));
    }
    if (i < 128*64) {               // W3T: [n=128][k=64]
        int n = i >> 6, k = i & 63;
        float v = W3[k*128 + n];
        __nv_bfloat16 h = __float2bfloat16(v);
        g_w3h[i] = h;
        g_w3l[i] = __float2bfloat16(v - __bfloat162float(h));
    }
}

// ---------------------------------------------------------------------------
// Kernel 1: ball query (unchanged, known good)
// ---------------------------------------------------------------------------
__global__ void bq_kernel() {
    int w    = (blockIdx.x * blockDim.x + threadIdx.x) >> 5;
    int lane = threadIdx.x & 31;
    if (w >= BATCH * SPTS) return;
    int b = w / SPTS, s = w % SPTS;
    const float4* xb4 = g_xyzw + (size_t)b * NPTS;
    float4 q = xb4[s];
    int* idx = g_idx + (size_t)w * KNB;
    int cnt = 0;
    int firstIdx = 0;
    bool haveFirst = false;
    unsigned lmask = (1u << lane) - 1u;

    float4 cur[4], nxt[4];
    #pragma unroll
    for (int t = 0; t < 4; t++) cur[t] = xb4[32*t + lane];
    #pragma unroll
    for (int t = 0; t < 4; t++) nxt[t] = xb4[128 + 32*t + lane];

    for (int j0 = 0; j0 < NPTS && cnt < KNB; j0 += 128) {
        unsigned m[4];
        bool hit[4];
        #pragma unroll
        for (int t = 0; t < 4; t++) {
            float4 p = cur[t];
            float dot = q.x*p.x + q.y*p.y + q.z*p.z;
            float d2  = q.w + p.w - 2.0f*dot;   // same formula as reference
            hit[t] = d2 < R2;
            m[t] = __ballot_sync(0xffffffffu, hit[t]);
        }
        #pragma unroll
        for (int t = 0; t < 4; t++) {
            cur[t] = nxt[t];
            int i = j0 + 256 + 32*t + lane;
            if (i >= NPTS) i -= NPTS;
            nxt[t] = xb4[i];
        }
        #pragma unroll
        for (int t = 0; t < 4; t++) {
            if (m[t] && !haveFirst) {
                firstIdx = j0 + 32*t + (__ffs(m[t]) - 1);
                haveFirst = true;
            }
            int pos = cnt + __popc(m[t] & lmask);
            if (hit[t] && pos < KNB) idx[pos] = j0 + 32*t + lane;
            cnt += __popc(m[t]);
        }
    }
    if (cnt < KNB && lane >= cnt) idx[lane] = firstIdx;
}

// ---------------------------------------------------------------------------
// Kernel 2: transpose features [B,C,N] -> [B,N,C]
// ---------------------------------------------------------------------------
__global__ void transpose_kernel(const float* __restrict__ f) {
    __shared__ float tile[32][33];
    int b  = blockIdx.z;
    int c0 = blockIdx.y * 32;
    int n0 = blockIdx.x * 32;
    int tx = threadIdx.x, ty = threadIdx.y;
    const float* src = f + ((size_t)b * CH) * NPTS;
    #pragma unroll
    for (int r = ty; r < 32; r += 8)
        tile[r][tx] = src[(size_t)(c0 + r) * NPTS + n0 + tx];
    __syncthreads();
    float* dst = g_featT + ((size_t)b * NPTS) * CH;
    #pragma unroll
    for (int r = ty; r < 32; r += 8)
        dst[(size_t)(n0 + r) * CH + c0 + tx] = tile[tx][r];
}

// ---------------------------------------------------------------------------
// Kernel 3: trivial outputs
// ---------------------------------------------------------------------------
__global__ void misc_kernel(const float* __restrict__ xyz, float* __restrict__ out) {
    int i = blockIdx.x * blockDim.x + threadIdx.x;
    if (i < N_XYZ_OUT) {
        int b = i / (SPTS * 3), r = i % (SPTS * 3);
        out[i] = xyz[(size_t)b * NPTS * 3 + r];
    }
    if (i < BATCH * SPTS) {
        out[OFF_SAMP + i] = (float)(i % SPTS);
    }
}

// ---------------------------------------------------------------------------
// Kernel 4: HMMA (mma.sync) MLP. Persistent CTAs, 256 threads = 8 warps.
// Tile = 4 centroids = 128 rows; warp w owns m-tile w (rows 16w..16w+15),
// so all A reads/writes are warp-local (no block syncs in the layer chain).
// fp32 precision via bf16 hi/lo split, 3 MMA terms per layer.
// ---------------------------------------------------------------------------
#define MLP_THREADS 256
#define SA  88     // A row stride (bf16 elems) — conflict-free ldmatrix
#define SW1 88
#define SW2 72
#define SW3 72
// smem byte offsets
#define OFF_AH   0          // 128*88*2 = 22528
#define OFF_AL   22528
#define OFF_W1H  45056      // 64*88*2 = 11264
#define OFF_W1L  56320
#define OFF_W2H  67584      // 64*72*2 = 9216
#define OFF_W2L  76800
#define OFF_W3H  86016      // 128*72*2 = 18432
#define OFF_W3L  104448
#define OFF_BIAS 122880     // 256 floats
#define OFF_PART 123904     // 2 * 8*64*4 = 4096
#define MLP_SMEM_BYTES 128000

__global__ void __launch_bounds__(MLP_THREADS)
mlp_kernel(const float* __restrict__ b1, const float* __restrict__ b2,
           const float* __restrict__ b3, float* __restrict__ out) {
    extern __shared__ char sm[];
    uint32_t sb = smem_to_u32(sm);
    int t = threadIdx.x, lane = t & 31, wid = t >> 5;

    // ---- stage weights (hi/lo, [N][K] row-major, padded strides) ----
    for (int i = t; i < 64*80; i += MLP_THREADS) {
        int n = i / 80, k = i % 80;
        *(__nv_bfloat16*)(sm + OFF_W1H + (n*SW1 + k)*2) = g_w1h[n*128 + k];
        *(__nv_bfloat16*)(sm + OFF_W1L + (n*SW1 + k)*2) = g_w1l[n*128 + k];
    }
    for (int i = t; i < 64*64; i += MLP_THREADS) {
        int n = i >> 6, k = i & 63;
        *(__nv_bfloat16*)(sm + OFF_W2H + (n*SW2 + k)*2) = g_w2h[i];
        *(__nv_bfloat16*)(sm + OFF_W2L + (n*SW2 + k)*2) = g_w2l[i];
    }
    for (int i = t; i < 128*64; i += MLP_THREADS) {
        int n = i >> 6, k = i & 63;
        *(__nv_bfloat16*)(sm + OFF_W3H + (n*SW3 + k)*2) = g_w3h[i];
        *(__nv_bfloat16*)(sm + OFF_W3L + (n*SW3 + k)*2) = g_w3l[i];
    }
    float* bias = (float*)(sm + OFF_BIAS);
    if (t < 64)  bias[t]       = b1[t];
    if (t < 64)  bias[64 + t]  = b2[t];
    if (t < 128) bias[128 + t] = b3[t];
    // zero A hi+lo once (cols 68..79 must stay zero; never written later)
    for (int i = t; i < 45056/16; i += MLP_THREADS)
        ((uint4*)(sm + OFF_AH))[i] = make_uint4(0,0,0,0);
    __syncthreads();

    // ---- per-thread fragment address precomputes ----
    int row0 = wid * 16;
    // A frag (m16k16): lanes 0-15 -> rows row0+l, k0; lanes 16-31 -> rows row0+(l-16), k0+8
    uint32_t a_off = (uint32_t)((row0 + (lane & 15)) * SA + ((lane >> 4) * 8)) * 2u;
    uint32_t aAH = sb + OFF_AH + a_off;
    uint32_t aAL = sb + OFF_AL + a_off;
    // B frag (k16n8) from W[N][K]: lanes 0-7 -> row n0+l,k0 ; lanes 8-15 -> n0+l-8,k0+8
    int bl = (lane < 8) ? lane : ((lane < 16) ? lane - 8 : 0);
    int bk = (lane >= 8 && lane < 16) ? 8 : 0;
    uint32_t b_off1 = (uint32_t)(bl*SW1 + bk) * 2u;
    uint32_t b_off2 = (uint32_t)(bl*SW2 + bk) * 2u;
    uint32_t b_off3 = (uint32_t)(bl*SW3 + bk) * 2u;
    int tq = lane & 3, tr = lane >> 2;

    const int ntiles = (BATCH * SPTS) / 4;   // 2048

    for (int tile = blockIdx.x; tile < ntiles; tile += gridDim.x) {
        // ================= gather (2 threads per row, warp-local rows) ======
        {
            int row = t >> 1, half = t & 1;
            int cid = tile*4 + (row >> 5);
            int bb = cid >> 12, s = cid & (SPTS-1);
            int n = g_idx[cid*KNB + (row & 31)];
            const float4* fr = (const float4*)(g_featT + ((size_t)bb*NPTS + n)*CH);
            float v[34];
            if (half == 0) {
                float4 pc = g_xyzw[(size_t)bb*NPTS + s];
                float4 pn = g_xyzw[(size_t)bb*NPTS + n];
                v[0] = pn.x - pc.x; v[1] = pn.y - pc.y; v[2] = pn.z - pc.z;
                #pragma unroll
                for (int j = 0; j < 7; j++) {
                    float4 q = fr[j];
                    v[3+4*j] = q.x; v[4+4*j] = q.y; v[5+4*j] = q.z; v[6+4*j] = q.w;
                }
                float4 q = fr[7];
                v[31] = q.x; v[32] = q.y; v[33] = q.z;      // feats 28..30
            } else {
                float4 q = fr[7];
                v[0] = q.w;                                   // feat 31
                #pragma unroll
                for (int j = 0; j < 8; j++) {
                    float4 r = fr[8+j];
                    v[1+4*j] = r.x; v[2+4*j] = r.y; v[3+4*j] = r.z; v[4+4*j] = r.w;
                }
                v[33] = 0.0f;                                 // col 67 pad
            }
            int base = half * 34;
            char* pH = sm + OFF_AH + (row*SA + base)*2;
            char* pL = sm + OFF_AL + (row*SA + base)*2;
            #pragma unroll
            for (int p = 0; p < 17; p++) {
                float a0 = v[2*p], a1 = v[2*p+1];
                __nv_bfloat16 h0 = __float2bfloat16(a0), h1 = __float2bfloat16(a1);
                *(uint32_t*)(pH + 4*p) = pack_bf2(a0, a1);   // hi (pack truncates same way)
                *(uint32_t*)(pL + 4*p) = pack_bf2(a0 - __bfloat162float(h0),
                                                  a1 - __bfloat162float(h1));
            }
        }
        __syncwarp();

        // ================= layer 1: K=80, N=64 =================
        {
            float acc[8][4];
            #pragma unroll
            for (int j = 0; j < 8; j++)
                #pragma unroll
                for (int i = 0; i < 4; i++) acc[j][i] = 0.0f;
            #pragma unroll
            for (int kt = 0; kt < 5; kt++) {
                uint32_t kb = (uint32_t)kt * 32u;   // 16 elems * 2B
                uint32_t ah0,ah1,ah2,ah3, al0,al1,al2,al3;
                ldm_x4(ah0,ah1,ah2,ah3, aAH + kb);
                ldm_x4(al0,al1,al2,al3, aAL + kb);
                #pragma unroll
                for (int j = 0; j < 8; j++) {
                    uint32_t wb = (uint32_t)(j*8*SW1 + kt*16) * 2u;
                    uint32_t bh0,bh1, bl0,bl1;
                    ldm_x2(bh0,bh1, sb + OFF_W1H + b_off1 + wb);
                    ldm_x2(bl0,bl1, sb + OFF_W1L + b_off1 + wb);
                    mma_bf16(acc[j], ah0,ah1,ah2,ah3, bh0,bh1);
                    mma_bf16(acc[j], ah0,ah1,ah2,ah3, bl0,bl1);
                    mma_bf16(acc[j], al0,al1,al2,al3, bh0,bh1);
                }
            }
            // epilogue: bias + relu -> split hi/lo -> A cols 0..63
            #pragma unroll
            for (int j = 0; j < 8; j++) {
                int c = 8*j + 2*tq;
                float x0 = fmaxf(acc[j][0] + bias[c],   0.0f);
                float x1 = fmaxf(acc[j][1] + bias[c+1], 0.0f);
                float x2 = fmaxf(acc[j][2] + bias[c],   0.0f);
                float x3 = fmaxf(acc[j][3] + bias[c+1], 0.0f);
                int ra = row0 + tr, rb = row0 + 8 + tr;
                __nv_bfloat16 h0=__float2bfloat16(x0), h1=__float2bfloat16(x1);
                __nv_bfloat16 h2=__float2bfloat16(x2), h3=__float2bfloat16(x3);
                *(uint32_t*)(sm + OFF_AH + (ra*SA + c)*2) = pack_bf2(x0, x1);
                *(uint32_t*)(sm + OFF_AH + (rb*SA + c)*2) = pack_bf2(x2, x3);
                *(uint32_t*)(sm + OFF_AL + (ra*SA + c)*2) =
                    pack_bf2(x0 - __bfloat162float(h0), x1 - __bfloat162float(h1));
                *(uint32_t*)(sm + OFF_AL + (rb*SA + c)*2) =
                    pack_bf2(x2 - __bfloat162float(h2), x3 - __bfloat162float(h3));
            }
        }
        __syncwarp();

        // ================= layer 2: K=64, N=64 =================
        {
            float acc[8][4];
            #pragma unroll
            for (int j = 0; j < 8; j++)
                #pragma unroll
                for (int i = 0; i < 4; i++) acc[j][i] = 0.0f;
            #pragma unroll
            for (int kt = 0; kt < 4; kt++) {
                uint32_t kb = (uint32_t)kt * 32u;
                uint32_t ah0,ah1,ah2,ah3, al0,al1,al2,al3;
                ldm_x4(ah0,ah1,ah2,ah3, aAH + kb);
                ldm_x4(al0,al1,al2,al3, aAL + kb);
                #pragma unroll
                for (int j = 0; j < 8; j++) {
                    uint32_t wb = (uint32_t)(j*8*SW2 + kt*16) * 2u;
                    uint32_t bh0,bh1, bl0,bl1;
                    ldm_x2(bh0,bh1, sb + OFF_W2H + b_off2 + wb);
                    ldm_x2(bl0,bl1, sb + OFF_W2L + b_off2 + wb);
                    mma_bf16(acc[j], ah0,ah1,ah2,ah3, bh0,bh1);
                    mma_bf16(acc[j], ah0,ah1,ah2,ah3, bl0,bl1);
                    mma_bf16(acc[j], al0,al1,al2,al3, bh0,bh1);
                }
            }
            const float* bias2 = bias + 64;
            #pragma unroll
            for (int j = 0; j < 8; j++) {
                int c = 8*j + 2*tq;
                float x0 = fmaxf(acc[j][0] + bias2[c],   0.0f);
                float x1 = fmaxf(acc[j][1] + bias2[c+1], 0.0f);
                float x2 = fmaxf(acc[j][2] + bias2[c],   0.0f);
                float x3 = fmaxf(acc[j][3] + bias2[c+1], 0.0f);
                int ra = row0 + tr, rb = row0 + 8 + tr;
                __nv_bfloat16 h0=__float2bfloat16(x0), h1=__float2bfloat16(x1);
                __nv_bfloat16 h2=__float2bfloat16(x2), h3=__float2bfloat16(x3);
                *(uint32_t*)(sm + OFF_AH + (ra*SA + c)*2) = pack_bf2(x0, x1);
                *(uint32_t*)(sm + OFF_AH + (rb*SA + c)*2) = pack_bf2(x2, x3);
                *(uint32_t*)(sm + OFF_AL + (ra*SA + c)*2) =
                    pack_bf2(x0 - __bfloat162float(h0), x1 - __bfloat162float(h1));
                *(uint32_t*)(sm + OFF_AL + (rb*SA + c)*2) =
                    pack_bf2(x2 - __bfloat162float(h2), x3 - __bfloat162float(h3));
            }
        }
        __syncwarp();

        // ================= layer 3: K=64, N=128 (two 64-col halves) ========
        const float* bias3 = bias + 128;
        #pragma unroll 1
        for (int nh = 0; nh < 2; nh++) {
            float acc[8][4];
            #pragma unroll
            for (int j = 0; j < 8; j++)
                #pragma unroll
                for (int i = 0; i < 4; i++) acc[j][i] = 0.0f;
            #pragma unroll
            for (int kt = 0; kt < 4; kt++) {
                uint32_t kb = (uint32_t)kt * 32u;
                uint32_t ah0,ah1,ah2,ah3, al0,al1,al2,al3;
                ldm_x4(ah0,ah1,ah2,ah3, aAH + kb);
                ldm_x4(al0,al1,al2,al3, aAL + kb);
                #pragma unroll
                for (int j = 0; j < 8; j++) {
                    uint32_t wb = (uint32_t)(((nh*64 + j*8)*SW3) + kt*16) * 2u;
                    uint32_t bh0,bh1, bl0,bl1;
                    ldm_x2(bh0,bh1, sb + OFF_W3H + b_off3 + wb);
                    ldm_x2(bl0,bl1, sb + OFF_W3L + b_off3 + wb);
                    mma_bf16(acc[j], ah0,ah1,ah2,ah3, bh0,bh1);
                    mma_bf16(acc[j], ah0,ah1,ah2,ah3, bl0,bl1);
                    mma_bf16(acc[j], al0,al1,al2,al3, bh0,bh1);
                }
            }
            // relu + in-register pool over this warp's 16 rows
            float* part = (float*)(sm + OFF_PART + nh*2048);
            #pragma unroll
            for (int j = 0; j < 8; j++) {
                int c = 64*nh + 8*j + 2*tq;
                float m0 = fmaxf(fmaxf(acc[j][0] + bias3[c],   0.0f),
                                 fmaxf(acc[j][2] + bias3[c],   0.0f));
                float m1 = fmaxf(fmaxf(acc[j][1] + bias3[c+1], 0.0f),
                                 fmaxf(acc[j][3] + bias3[c+1], 0.0f));
                #pragma unroll
                for (int sh = 4; sh <= 16; sh <<= 1) {
                    m0 = fmaxf(m0, __shfl_xor_sync(0xffffffffu, m0, sh));
                    m1 = fmaxf(m1, __shfl_xor_sync(0xffffffffu, m1, sh));
                }
                if (tr == 0) {
                    part[wid*64 + 8*j + 2*tq]     = m0;
                    part[wid*64 + 8*j + 2*tq + 1] = m1;
                }
            }
            __syncthreads();
            // combine warp pairs (centroid = 2 warps) + store
            {
                int cent = t >> 6, col = t & 63;
                float v = fmaxf(part[(2*cent)*64 + col], part[(2*cent+1)*64 + col]);
                int cid = tile*4 + cent;
                int bb = cid >> 12, s = cid & (SPTS-1);
                out[OFF_FEAT + ((size_t)bb * OUTC + 64*nh + col) * SPTS + s] = v;
            }
        }
    }
}

// ---------------------------------------------------------------------------
extern "C" void kernel_launch(void* const* d_in, const int* in_sizes, int n_in,
                              void* d_out, int out_size) {
    const float* xyz      = (const float*)d_in[0];
    const float* features = (const float*)d_in[1];
    const float* W1 = (const float*)d_in[2];
    const float* b1 = (const float*)d_in[3];
    const float* W2 = (const float*)d_in[4];
    const float* b2 = (const float*)d_in[5];
    const float* W3 = (const float*)d_in[6];
    const float* b3 = (const float*)d_in[7];
    float* out = (float*)d_out;

    // pack xyz + |p|^2
    prep_kernel<<<(BATCH*NPTS + 255)/256, 256>>>(xyz);

    // weight transpose + hi/lo bf16 split
    wprep_kernel<<<(64*128 + 255)/256, 256>>>(W1, W2, W3);

    // ball query: one warp per centroid, 128-wide chunks
    bq_kernel<<<(BATCH*SPTS*32)/256, 256>>>();

    // feature transpose [B,C,N] -> [B,N,C]
    {
        dim3 g(NPTS/32, CH/32, BATCH);
        dim3 blk(32, 8);
        transpose_kernel<<<g, blk>>>(features);
    }

    // trivial outputs
    misc_kernel<<<(N_XYZ_OUT + 255)/256, 256>>>(xyz, out);

    // HMMA MLP: persistent 148 CTAs, 256 threads, 4 centroids per tile
    static bool attr_done = false;
    if (!attr_done) {
        cudaFuncSetAttribute(mlp_kernel, cudaFuncAttributeMaxDynamicSharedMemorySize,
                             MLP_SMEM_BYTES);
        attr_done = true;
    }
    mlp_kernel<<<148, MLP_THREADS, MLP_SMEM_BYTES>>>(b1, b2, b3, out);
}